// round 1
// baseline (speedup 1.0000x reference)
#include <cuda_runtime.h>
#include <cstdint>

// Problem constants (fixed shapes for this problem)
#define PB 4
#define PN 65536
#define PC 128
#define PS 32768
#define PBN (PB * PN)          // 262144 points
#define CG (PC / 4)            // 32 float4 channel-groups per point

// Scratch: segment sums [S, C] as float4 and counts [S].
// __device__ globals (no allocation allowed in kernel_launch).
__device__ float4 g_segsum[PS * CG];   // 16 MB
__device__ int    g_cnt[PS];

// ---------------------------------------------------------------------------
// Pass 1: scatter-reduce x into per-segment sums + counts.
// One warp per point: lanes cover the 32 float4 channel groups (512B row).
// Segment id load is warp-uniform (broadcast).
// ---------------------------------------------------------------------------
__global__ __launch_bounds__(256) void k_accum(
    const float4* __restrict__ x,       // [BN, 32] float4
    const int*    __restrict__ ul_idx,  // [BN]
    float4*       __restrict__ segsum,  // [S, 32] float4
    int*          __restrict__ cnt)     // [S]
{
    int t    = blockIdx.x * blockDim.x + threadIdx.x;
    int p    = t >> 5;
    int lane = t & 31;
    if (p >= PBN) return;

    int seg = __ldg(&ul_idx[p]);
    float4 v = __ldg(&x[(size_t)p * CG + lane]);

    float4* dst = &segsum[(size_t)seg * CG + lane];
    asm volatile("red.global.add.v4.f32 [%0], {%1, %2, %3, %4};"
                 :: "l"(dst), "f"(v.x), "f"(v.y), "f"(v.z), "f"(v.w)
                 : "memory");

    if (lane == 0) atomicAdd(&cnt[seg], 1);
}

// ---------------------------------------------------------------------------
// Pass 2: fused normalize + (scatter->gather collapse) + mask + store.
// out[p, :] = valid(p) ? mask[p] * segsum[seg(p), :] / max(cnt,1) : 0
// where seg(p) = ul_idx[rep_flat(p)], rep_flat from idx, and valid checks
// that rep_flat is actually the representative slot (faithful to reference).
// One warp per point; seg_sum gather hits L2 (16 MB footprint).
// ---------------------------------------------------------------------------
__global__ __launch_bounds__(256) void k_out(
    const float4* __restrict__ segsum,     // [S, 32] float4
    const int*    __restrict__ cnt,        // [S]
    const int*    __restrict__ idx,        // [BN, 2]
    const float*  __restrict__ mask,       // [BN]
    const int*    __restrict__ ul_idx,     // [BN]
    const int*    __restrict__ ul_idx_inv, // [S]
    float4*       __restrict__ out)        // [BN, 32] float4
{
    int t    = blockIdx.x * blockDim.x + threadIdx.x;
    int p    = t >> 5;
    int lane = t & 31;
    if (p >= PBN) return;

    int seg = 0;
    float scale = 0.0f;
    if (lane == 0) {
        int i0  = __ldg(&idx[2 * p]);
        int i1  = __ldg(&idx[2 * p + 1]);
        int rep = i0 * PN + i1;
        // guard against out-of-range (shouldn't happen on valid data)
        rep = min(max(rep, 0), PBN - 1);
        seg = __ldg(&ul_idx[rep]);
        int c = __ldg(&cnt[seg]);
        bool valid = (__ldg(&ul_idx_inv[seg]) == rep);
        float m = __ldg(&mask[p]);
        scale = valid ? (m / (float)max(c, 1)) : 0.0f;
    }
    seg   = __shfl_sync(0xffffffffu, seg, 0);
    scale = __shfl_sync(0xffffffffu, scale, 0);

    float4 v = __ldg(&segsum[(size_t)seg * CG + lane]);
    v.x *= scale; v.y *= scale; v.z *= scale; v.w *= scale;
    out[(size_t)p * CG + lane] = v;
}

// ---------------------------------------------------------------------------
// Launch: memset scratch -> accumulate -> fused output.
// Inputs (metadata order): x[f32 BN*C], idx[i32 BN*2], mask[f32 BN],
//                          ul_idx[i32 BN], ul_idx_inv[i32 S]
// Output: f32 [B, N, C]
// ---------------------------------------------------------------------------
extern "C" void kernel_launch(void* const* d_in, const int* in_sizes, int n_in,
                              void* d_out, int out_size)
{
    const float4* x          = (const float4*)d_in[0];
    const int*    idx        = (const int*)d_in[1];
    const float*  mask       = (const float*)d_in[2];
    const int*    ul_idx     = (const int*)d_in[3];
    const int*    ul_idx_inv = (const int*)d_in[4];
    float4*       out        = (float4*)d_out;

    void* segsum_ptr = nullptr;
    void* cnt_ptr    = nullptr;
    cudaGetSymbolAddress(&segsum_ptr, g_segsum);
    cudaGetSymbolAddress(&cnt_ptr, g_cnt);

    cudaMemsetAsync(segsum_ptr, 0, sizeof(float4) * PS * CG, 0);
    cudaMemsetAsync(cnt_ptr,    0, sizeof(int) * PS, 0);

    const int threads = 256;
    const int total   = PBN * 32;               // one warp per point
    const int blocks  = (total + threads - 1) / threads;

    k_accum<<<blocks, threads>>>(x, ul_idx, (float4*)segsum_ptr, (int*)cnt_ptr);
    k_out<<<blocks, threads>>>((const float4*)segsum_ptr, (const int*)cnt_ptr,
                               idx, mask, ul_idx, ul_idx_inv, out);
}

// round 2
// speedup vs baseline: 1.3237x; 1.3237x over previous
#include <cuda_runtime.h>
#include <cstdint>

// Problem constants (fixed shapes for this problem)
#define PB 4
#define PN 65536
#define PC 128
#define PS 32768
#define PBN (PB * PN)          // 262144 points
#define CG (PC / 4)            // 32 float4 channel-groups per point

// Scratch (no allocation allowed in kernel_launch).
__device__ float4 g_segsum[PS * CG];   // 16 MB  segment sums
__device__ int    g_cnt[PS];           // counts
__device__ int2   g_rec[PBN];          // per-point {seg, scale-as-int}, 2 MB

// ---------------------------------------------------------------------------
// Pass 1: scatter-reduce x into per-segment sums + counts.
// One warp per point: lanes cover the 32 float4 channel groups (512B row).
// ---------------------------------------------------------------------------
__global__ __launch_bounds__(256) void k_accum(
    const float4* __restrict__ x,       // [BN, 32] float4
    const int*    __restrict__ ul_idx,  // [BN]
    float4*       __restrict__ segsum,  // [S, 32] float4
    int*          __restrict__ cnt)     // [S]
{
    int t    = blockIdx.x * blockDim.x + threadIdx.x;
    int p    = t >> 5;
    int lane = t & 31;
    if (p >= PBN) return;

    int seg = __ldg(&ul_idx[p]);
    float4 v = __ldg(&x[(size_t)p * CG + lane]);

    float4* dst = &segsum[(size_t)seg * CG + lane];
    asm volatile("red.global.add.v4.f32 [%0], {%1, %2, %3, %4};"
                 :: "l"(dst), "f"(v.x), "f"(v.y), "f"(v.z), "f"(v.w)
                 : "memory");

    if (lane == 0) atomicAdd(&cnt[seg], 1);
}

// ---------------------------------------------------------------------------
// Pass 1.5: per-point scalar chain, hoisted out of the hot output kernel.
// rec[p] = {seg(p), mask[p]/cnt (or 0 if rep-slot mismatch)}
// ---------------------------------------------------------------------------
__global__ __launch_bounds__(256) void k_prep(
    const int*   __restrict__ cnt,        // [S]
    const int*   __restrict__ idx,        // [BN, 2]
    const float* __restrict__ mask,       // [BN]
    const int*   __restrict__ ul_idx,     // [BN]
    const int*   __restrict__ ul_idx_inv, // [S]
    int2*        __restrict__ rec)        // [BN]
{
    int p = blockIdx.x * blockDim.x + threadIdx.x;
    if (p >= PBN) return;

    int i0  = __ldg(&idx[2 * p]);
    int i1  = __ldg(&idx[2 * p + 1]);
    int repv = i0 * PN + i1;
    int repc = min(max(repv, 0), PBN - 1);      // clamp for safety
    int seg = __ldg(&ul_idx[repc]);
    int c   = __ldg(&cnt[seg]);
    bool valid = (__ldg(&ul_idx_inv[seg]) == repv);
    float m = __ldg(&mask[p]);
    float scale = valid ? (m / (float)max(c, 1)) : 0.0f;

    rec[p] = make_int2(seg, __float_as_int(scale));
}

// ---------------------------------------------------------------------------
// Pass 2: each warp handles 4 points -> 4 independent L2 gathers in flight
// (MLP 4 per warp) + 4 streaming stores. segsum (16 MB) is L2-resident.
// ---------------------------------------------------------------------------
__global__ __launch_bounds__(256) void k_out(
    const float4* __restrict__ segsum,  // [S, 32] float4
    const int2*   __restrict__ rec,     // [BN]
    float4*       __restrict__ out)     // [BN, 32] float4
{
    int t    = blockIdx.x * blockDim.x + threadIdx.x;
    int w    = t >> 5;                  // global warp id
    int lane = t & 31;
    int p0   = w * 4;
    if (p0 >= PBN) return;

    // lanes 0..3 fetch the 4 point records, broadcast via shfl
    int2 r = make_int2(0, 0);
    if (lane < 4) r = __ldg(&rec[p0 + lane]);

    int   seg0 = __shfl_sync(0xffffffffu, r.x, 0);
    int   seg1 = __shfl_sync(0xffffffffu, r.x, 1);
    int   seg2 = __shfl_sync(0xffffffffu, r.x, 2);
    int   seg3 = __shfl_sync(0xffffffffu, r.x, 3);
    float s0 = __int_as_float(__shfl_sync(0xffffffffu, r.y, 0));
    float s1 = __int_as_float(__shfl_sync(0xffffffffu, r.y, 1));
    float s2 = __int_as_float(__shfl_sync(0xffffffffu, r.y, 2));
    float s3 = __int_as_float(__shfl_sync(0xffffffffu, r.y, 3));

    // 4 independent gathers (batched by the compiler -> MLP 4)
    float4 v0 = __ldg(&segsum[(size_t)seg0 * CG + lane]);
    float4 v1 = __ldg(&segsum[(size_t)seg1 * CG + lane]);
    float4 v2 = __ldg(&segsum[(size_t)seg2 * CG + lane]);
    float4 v3 = __ldg(&segsum[(size_t)seg3 * CG + lane]);

    v0.x *= s0; v0.y *= s0; v0.z *= s0; v0.w *= s0;
    v1.x *= s1; v1.y *= s1; v1.z *= s1; v1.w *= s1;
    v2.x *= s2; v2.y *= s2; v2.z *= s2; v2.w *= s2;
    v3.x *= s3; v3.y *= s3; v3.z *= s3; v3.w *= s3;

    out[(size_t)(p0 + 0) * CG + lane] = v0;
    out[(size_t)(p0 + 1) * CG + lane] = v1;
    out[(size_t)(p0 + 2) * CG + lane] = v2;
    out[(size_t)(p0 + 3) * CG + lane] = v3;
}

// ---------------------------------------------------------------------------
// Launch: memset scratch -> accumulate -> prep records -> fused output.
// Inputs (metadata order): x[f32 BN*C], idx[i32 BN*2], mask[f32 BN],
//                          ul_idx[i32 BN], ul_idx_inv[i32 S]
// ---------------------------------------------------------------------------
extern "C" void kernel_launch(void* const* d_in, const int* in_sizes, int n_in,
                              void* d_out, int out_size)
{
    const float4* x          = (const float4*)d_in[0];
    const int*    idx        = (const int*)d_in[1];
    const float*  mask       = (const float*)d_in[2];
    const int*    ul_idx     = (const int*)d_in[3];
    const int*    ul_idx_inv = (const int*)d_in[4];
    float4*       out        = (float4*)d_out;

    void *segsum_ptr = nullptr, *cnt_ptr = nullptr, *rec_ptr = nullptr;
    cudaGetSymbolAddress(&segsum_ptr, g_segsum);
    cudaGetSymbolAddress(&cnt_ptr, g_cnt);
    cudaGetSymbolAddress(&rec_ptr, g_rec);

    cudaMemsetAsync(segsum_ptr, 0, sizeof(float4) * PS * CG, 0);
    cudaMemsetAsync(cnt_ptr,    0, sizeof(int) * PS, 0);

    const int threads = 256;

    // accumulate: one warp per point
    {
        int total  = PBN * 32;
        int blocks = (total + threads - 1) / threads;
        k_accum<<<blocks, threads>>>(x, ul_idx, (float4*)segsum_ptr, (int*)cnt_ptr);
    }

    // prep: one thread per point
    {
        int blocks = (PBN + threads - 1) / threads;
        k_prep<<<blocks, threads>>>((const int*)cnt_ptr, idx, mask, ul_idx,
                                    ul_idx_inv, (int2*)rec_ptr);
    }

    // out: one warp per 4 points
    {
        int total  = (PBN / 4) * 32;
        int blocks = (total + threads - 1) / threads;
        k_out<<<blocks, threads>>>((const float4*)segsum_ptr,
                                   (const int2*)rec_ptr, out);
    }
}